// round 8
// baseline (speedup 1.0000x reference)
#include <cuda_runtime.h>
#include <cuda_bf16.h>
#include <cstdint>
#include <math.h>

// ---------------- problem constants ----------------
#define T_TOK   8192
#define DIM     2048
#define NH      16
#define NKV     8
#define HD      128
#define S_LEN   1024
#define B_SZ    8
#define KV_DIM  1024      // NKV * HD
#define N_REP   2

// ---------------- scratch ----------------
__device__ float g_q[T_TOK * DIM];
__device__ float g_k[T_TOK * KV_DIM];
__device__ float g_v[T_TOK * KV_DIM];

// bf16 hi/lo splits
__device__ __nv_bfloat16 g_xh[T_TOK * DIM];   // x split, then reused as q split (hi)
__device__ __nv_bfloat16 g_xl[T_TOK * DIM];   //                                (lo)
__device__ __nv_bfloat16 g_ah[T_TOK * DIM];   // attn out split hi
__device__ __nv_bfloat16 g_al[T_TOK * DIM];   // attn out split lo
__device__ __nv_bfloat16 g_kh[T_TOK * KV_DIM];
__device__ __nv_bfloat16 g_kl[T_TOK * KV_DIM];
__device__ __nv_bfloat16 g_vh[T_TOK * KV_DIM];
__device__ __nv_bfloat16 g_vl[T_TOK * KV_DIM];
// transposed bf16 hi/lo weights: [N, K] row-major (K contiguous)
__device__ __nv_bfloat16 g_wqTh[DIM * DIM];
__device__ __nv_bfloat16 g_wqTl[DIM * DIM];
__device__ __nv_bfloat16 g_wkTh[KV_DIM * DIM];
__device__ __nv_bfloat16 g_wkTl[KV_DIM * DIM];
__device__ __nv_bfloat16 g_wvTh[KV_DIM * DIM];
__device__ __nv_bfloat16 g_wvTl[KV_DIM * DIM];
__device__ __nv_bfloat16 g_woTh[DIM * DIM];
__device__ __nv_bfloat16 g_woTl[DIM * DIM];

// ================= low-level helpers (sm_80-class PTX only) =================
__device__ __forceinline__ uint32_t smem_to_u32(const void* smem_ptr) {
    uint32_t addr;
    asm("{ .reg .u64 tmp; cvta.to.shared.u64 tmp, %1; cvt.u32.u64 %0, tmp; }"
        : "=r"(addr) : "l"(smem_ptr));
    return addr;
}

#define CP_ASYNC16(dst_u32, src_ptr) \
    asm volatile("cp.async.cg.shared.global [%0], [%1], 16;" \
                 :: "r"(dst_u32), "l"(src_ptr) : "memory")
#define CP_COMMIT() asm volatile("cp.async.commit_group;" ::: "memory")
#define CP_WAIT0()  asm volatile("cp.async.wait_group 0;" ::: "memory")
#define CP_WAIT1()  asm volatile("cp.async.wait_group 1;" ::: "memory")

__device__ __forceinline__ void ldm_x4(uint32_t* r, uint32_t addr) {
    asm volatile("ldmatrix.sync.aligned.m8n8.x4.shared.b16 {%0,%1,%2,%3}, [%4];"
                 : "=r"(r[0]), "=r"(r[1]), "=r"(r[2]), "=r"(r[3]) : "r"(addr));
}
__device__ __forceinline__ void ldm_x2(uint32_t* r, uint32_t addr) {
    asm volatile("ldmatrix.sync.aligned.m8n8.x2.shared.b16 {%0,%1}, [%2];"
                 : "=r"(r[0]), "=r"(r[1]) : "r"(addr));
}
__device__ __forceinline__ void ldm_x2_trans(uint32_t* r, uint32_t addr) {
    asm volatile("ldmatrix.sync.aligned.m8n8.x2.trans.shared.b16 {%0,%1}, [%2];"
                 : "=r"(r[0]), "=r"(r[1]) : "r"(addr));
}
__device__ __forceinline__ void mma16816(float* c, const uint32_t* a, const uint32_t* b) {
    asm volatile("mma.sync.aligned.m16n8k16.row.col.f32.bf16.bf16.f32 "
                 "{%0,%1,%2,%3}, {%4,%5,%6,%7}, {%8,%9}, {%0,%1,%2,%3};"
                 : "+f"(c[0]), "+f"(c[1]), "+f"(c[2]), "+f"(c[3])
                 : "r"(a[0]), "r"(a[1]), "r"(a[2]), "r"(a[3]), "r"(b[0]), "r"(b[1]));
}
// pack two fp32 into bf16x2 word: low half = first arg, high half = second
__device__ __forceinline__ uint32_t packbf(float lo, float hi) {
    uint32_t r;
    asm("cvt.rn.bf16x2.f32 %0, %1, %2;" : "=r"(r) : "f"(hi), "f"(lo));
    return r;
}

// ================= bf16x3 mma.sync GEMM =================
// C[M,N] = A[M,K] @ W[K,N];  A as (Ah+Al) bf16 [M,K] K-major,
// W^T as (Bh+Bl) bf16 [N,K] K-major.  CTA tile 128x128, K-tile 32, 2-stage cp.async.
#define GT_ROWB   80
#define GT_TILE   (128 * GT_ROWB)          // 10240 B
#define GT_STAGE  (4 * GT_TILE)            // 40960 B
#define GT_TOTAL  (2 * GT_STAGE)           // 81920 B

__global__ __launch_bounds__(256, 2)
void gemm_mma(const __nv_bfloat16* __restrict__ Ah, const __nv_bfloat16* __restrict__ Al,
              const __nv_bfloat16* __restrict__ Bh, const __nv_bfloat16* __restrict__ Bl,
              float* __restrict__ C, int Ncols, int K)
{
    extern __shared__ char smc[];
    const uint32_t sbase = smem_to_u32(smc);

    const int tid  = threadIdx.x;
    const int lane = tid & 31;
    const int wid  = tid >> 5;
    const int bx = blockIdx.x;
    const int by = blockIdx.y;
    const int m0 = (wid & 1) * 64;
    const int n0 = (wid >> 1) * 32;

    const int ch0 = tid;
    const int ch1 = tid + 256;
    const int r0c = ch0 >> 2, c0c = ch0 & 3;
    const int r1c = ch1 >> 2, c1c = ch1 & 3;

    const size_t ga0 = (size_t)(by * 128 + r0c) * K + c0c * 8;
    const size_t ga1 = (size_t)(by * 128 + r1c) * K + c1c * 8;
    const size_t gb0 = (size_t)(bx * 128 + r0c) * K + c0c * 8;
    const size_t gb1 = (size_t)(bx * 128 + r1c) * K + c1c * 8;
    const uint32_t so0 = r0c * GT_ROWB + c0c * 16;
    const uint32_t so1 = r1c * GT_ROWB + c1c * 16;

    float acc[4][4][4];
#pragma unroll
    for (int i = 0; i < 4; i++)
#pragma unroll
        for (int j = 0; j < 4; j++)
#pragma unroll
            for (int e = 0; e < 4; e++) acc[i][j][e] = 0.f;

    const int n_kt = K >> 5;

    const uint32_t a_row = (uint32_t)(m0 + (lane & 15));
    const uint32_t a_coloff = (uint32_t)((lane >> 4) * 16);
    const uint32_t b_row = (uint32_t)(n0 + (lane & 7));
    const uint32_t b_coloff = (uint32_t)(((lane >> 3) & 1) * 16);

    {
        const uint32_t st = sbase;
        CP_ASYNC16(st + 0 * GT_TILE + so0, Ah + ga0);
        CP_ASYNC16(st + 0 * GT_TILE + so1, Ah + ga1);
        CP_ASYNC16(st + 1 * GT_TILE + so0, Al + ga0);
        CP_ASYNC16(st + 1 * GT_TILE + so1, Al + ga1);
        CP_ASYNC16(st + 2 * GT_TILE + so0, Bh + gb0);
        CP_ASYNC16(st + 2 * GT_TILE + so1, Bh + gb1);
        CP_ASYNC16(st + 3 * GT_TILE + so0, Bl + gb0);
        CP_ASYNC16(st + 3 * GT_TILE + so1, Bl + gb1);
        CP_COMMIT();
    }

    for (int kt = 0; kt < n_kt; kt++) {
        const int cur = kt & 1;
        if (kt + 1 < n_kt) {
            const uint32_t st = sbase + (cur ^ 1) * GT_STAGE;
            const size_t ko = (size_t)(kt + 1) * 32;
            CP_ASYNC16(st + 0 * GT_TILE + so0, Ah + ga0 + ko);
            CP_ASYNC16(st + 0 * GT_TILE + so1, Ah + ga1 + ko);
            CP_ASYNC16(st + 1 * GT_TILE + so0, Al + ga0 + ko);
            CP_ASYNC16(st + 1 * GT_TILE + so1, Al + ga1 + ko);
            CP_ASYNC16(st + 2 * GT_TILE + so0, Bh + gb0 + ko);
            CP_ASYNC16(st + 2 * GT_TILE + so1, Bh + gb1 + ko);
            CP_ASYNC16(st + 3 * GT_TILE + so0, Bl + gb0 + ko);
            CP_ASYNC16(st + 3 * GT_TILE + so1, Bl + gb1 + ko);
            CP_COMMIT();
            CP_WAIT1();
        } else {
            CP_WAIT0();
        }
        __syncthreads();

        const uint32_t st = sbase + cur * GT_STAGE;
        const uint32_t sAh = st;
        const uint32_t sAl = st + 1 * GT_TILE;
        const uint32_t sBh = st + 2 * GT_TILE;
        const uint32_t sBl = st + 3 * GT_TILE;

#pragma unroll
        for (int ks = 0; ks < 2; ks++) {
            const uint32_t kb = ks * 32;
            uint32_t af[4][4], bh[4][2], bl[4][2];
            // load Ah, Bh, Bl frags (both B sets stay live)
#pragma unroll
            for (int mt = 0; mt < 4; mt++)
                ldm_x4(af[mt], sAh + (a_row + mt * 16) * GT_ROWB + kb + a_coloff);
#pragma unroll
            for (int nt = 0; nt < 4; nt++) {
                ldm_x2(bh[nt], sBh + (b_row + nt * 8) * GT_ROWB + kb + b_coloff);
                ldm_x2(bl[nt], sBl + (b_row + nt * 8) * GT_ROWB + kb + b_coloff);
            }
            // pass 1: Ahi * Bhi ; pass 2: Ahi * Blo
#pragma unroll
            for (int mt = 0; mt < 4; mt++)
#pragma unroll
                for (int nt = 0; nt < 4; nt++) {
                    mma16816(acc[mt][nt], af[mt], bh[nt]);
                    mma16816(acc[mt][nt], af[mt], bl[nt]);
                }
            // pass 3: Alo * Bhi (reload A only)
#pragma unroll
            for (int mt = 0; mt < 4; mt++)
                ldm_x4(af[mt], sAl + (a_row + mt * 16) * GT_ROWB + kb + a_coloff);
#pragma unroll
            for (int mt = 0; mt < 4; mt++)
#pragma unroll
                for (int nt = 0; nt < 4; nt++)
                    mma16816(acc[mt][nt], af[mt], bh[nt]);
        }
        __syncthreads();
    }

    const int g  = lane >> 2;
    const int tg = (lane & 3) * 2;
#pragma unroll
    for (int mt = 0; mt < 4; mt++) {
        const int r = by * 128 + m0 + mt * 16 + g;
#pragma unroll
        for (int nt = 0; nt < 4; nt++) {
            const int cc = bx * 128 + n0 + nt * 8 + tg;
            *(float2*)(C + (size_t)r * Ncols + cc) =
                make_float2(acc[mt][nt][0], acc[mt][nt][1]);
            *(float2*)(C + (size_t)(r + 8) * Ncols + cc) =
                make_float2(acc[mt][nt][2], acc[mt][nt][3]);
        }
    }
}

// ---------------- fp32 -> bf16 hi/lo split ----------------
__global__ __launch_bounds__(256)
void convert_split(const float* __restrict__ X, __nv_bfloat16* __restrict__ H,
                   __nv_bfloat16* __restrict__ L, int total)
{
    int i = blockIdx.x * blockDim.x + threadIdx.x;
    if (i >= total) return;
    float v = X[i];
    __nv_bfloat16 h = __float2bfloat16(v);
    H[i] = h;
    L[i] = __float2bfloat16(v - __bfloat162float(h));
}

// ---------------- W[K,N] -> W^T hi/lo bf16 [N,K] ----------------
__global__ __launch_bounds__(256)
void transpose_convert(const float* __restrict__ W, __nv_bfloat16* __restrict__ Th,
                       __nv_bfloat16* __restrict__ Tl, int K, int N)
{
    __shared__ float t[32][33];
    int n0 = blockIdx.x * 32, k0 = blockIdx.y * 32;
    int tx = threadIdx.x & 31, ty = threadIdx.x >> 5;
#pragma unroll
    for (int j = 0; j < 4; j++)
        t[ty + j * 8][tx] = W[(size_t)(k0 + ty + j * 8) * N + n0 + tx];
    __syncthreads();
#pragma unroll
    for (int j = 0; j < 4; j++) {
        float v = t[tx][ty + j * 8];
        __nv_bfloat16 h = __float2bfloat16(v);
        __nv_bfloat16 l = __float2bfloat16(v - __bfloat162float(h));
        size_t o = (size_t)(n0 + ty + j * 8) * K + k0 + tx;
        Th[o] = h;
        Tl[o] = l;
    }
}

// ---------------- RoPE + bf16 hi/lo split ----------------
__global__ __launch_bounds__(256)
void rope_split(const float* __restrict__ src, const int* __restrict__ positions,
                __nv_bfloat16* __restrict__ H, __nv_bfloat16* __restrict__ L,
                int n_heads, float scale, int total)
{
    int idx = blockIdx.x * blockDim.x + threadIdx.x;
    if (idx >= total) return;
    int pair = idx & 63;
    int h    = (idx >> 6) % n_heads;
    int t    = idx / (64 * n_heads);
    double inv = pow(10000.0, -(double)(2 * pair) / 128.0);
    double ang = (double)positions[t] * inv;
    float c = (float)cos(ang);
    float s = (float)sin(ang);
    size_t o = (size_t)t * (n_heads * HD) + h * HD + 2 * pair;
    float xr = src[o], xi = src[o + 1];
    float vr = (xr * c - xi * s) * scale;
    float vi = (xr * s + xi * c) * scale;
    __nv_bfloat16 hr = __float2bfloat16(vr);
    __nv_bfloat16 hi = __float2bfloat16(vi);
    H[o]     = hr;
    H[o + 1] = hi;
    L[o]     = __float2bfloat16(vr - __bfloat162float(hr));
    L[o + 1] = __float2bfloat16(vi - __bfloat162float(hi));
}

// ================= mma.sync flash attention (causal, GQA rep=2) =================
// BQ=128, BK=64. grid (S/128, NH, B), 256 threads (8 warps; warp w owns q rows w*16..+15).
// smem: Qh,Ql [128][128]bf16 + double-buffered Kh,Kl,Vh,Vl [64][128]bf16; row stride 272 B.
#define AQ_ROWB 272
#define AQ_TILE (128 * AQ_ROWB)        // 34816
#define AKV_TILE (64 * AQ_ROWB)        // 17408
#define AKV_BUF (4 * AKV_TILE)         // 69632
#define AT_SMEM (2 * AQ_TILE + 2 * AKV_BUF)   // 208896 B -> 1 CTA/SM

__global__ __launch_bounds__(256, 1)
void attn_mma(const __nv_bfloat16* __restrict__ qh, const __nv_bfloat16* __restrict__ ql,
              const __nv_bfloat16* __restrict__ kh, const __nv_bfloat16* __restrict__ kl,
              const __nv_bfloat16* __restrict__ vhp, const __nv_bfloat16* __restrict__ vlp,
              __nv_bfloat16* __restrict__ oh, __nv_bfloat16* __restrict__ ol)
{
    extern __shared__ char smb[];
    const uint32_t sb  = smem_to_u32(smb);
    const uint32_t sQh = sb;
    const uint32_t sQl = sb + AQ_TILE;
    const uint32_t kv0 = sb + 2 * AQ_TILE;

    const int tid  = threadIdx.x;
    const int lane = tid & 31;
    const int wid  = tid >> 5;
    const int qt = blockIdx.x, h = blockIdx.y, b = blockIdx.z;
    const int kvh = h >> 1;
    const int q0 = qt * 128;
    const int m0 = wid * 16;
    const int g  = lane >> 2;
    const int tg = lane & 3;

    // --- Q tiles (hi+lo), 128 rows, loaded once ---
    {
        const __nv_bfloat16* srcH = qh + (size_t)(b * S_LEN + q0) * DIM + h * HD;
        const __nv_bfloat16* srcL = ql + (size_t)(b * S_LEN + q0) * DIM + h * HD;
        for (int c = tid; c < 2048; c += 256) {
            int r = c >> 4, cc = c & 15;
            CP_ASYNC16(sQh + r * AQ_ROWB + cc * 16, srcH + (size_t)r * DIM + cc * 8);
            CP_ASYNC16(sQl + r * AQ_ROWB + cc * 16, srcL + (size_t)r * DIM + cc * 8);
        }
        CP_COMMIT();
    }

    const size_t kvbase0 = (size_t)(b * S_LEN) * KV_DIM + kvh * HD;

    // prologue: KV tile 0 -> buffer 0
    {
        const __nv_bfloat16* pKh = kh + kvbase0;
        const __nv_bfloat16* pKl = kl + kvbase0;
        const __nv_bfloat16* pVh = vhp + kvbase0;
        const __nv_bfloat16* pVl = vlp + kvbase0;
        for (int c = tid; c < 1024; c += 256) {
            int r = c >> 4, cc = c & 15;
            uint32_t so = r * AQ_ROWB + cc * 16;
            size_t go = (size_t)r * KV_DIM + cc * 8;
            CP_ASYNC16(kv0 + 0 * AKV_TILE + so, pKh + go);
            CP_ASYNC16(kv0 + 1 * AKV_TILE + so, pKl + go);
            CP_ASYNC16(kv0 + 2 * AKV_TILE + so, pVh + go);
            CP_ASYNC16(kv0 + 3 * AKV_TILE + so, pVl + go);
        }
        CP_COMMIT();
    }

    float oacc[16][4];
#pragma unroll
    for (int nt = 0; nt < 16; nt++)
#pragma unroll
        for (int e = 0; e < 4; e++) oacc[nt][e] = 0.f;
    float mst0 = -1e30f, mst1 = -1e30f, lst0 = 0.f, lst1 = 0.f;

    const uint32_t qa_off = (uint32_t)((m0 + (lane & 15)) * AQ_ROWB + (lane >> 4) * 16);
    const uint32_t kb_row = (uint32_t)((lane & 7) * AQ_ROWB + ((lane >> 3) & 1) * 16);
    const uint32_t v_row  = (uint32_t)((lane & 15) * AQ_ROWB);

    const int ktmax = 2 * qt + 1;
    for (int kt = 0; kt <= ktmax; kt++) {
        const int cur = kt & 1;
        CP_WAIT0();
        __syncthreads();

        // prefetch next KV tile into the other buffer (overlaps with compute below)
        if (kt < ktmax) {
            const uint32_t kvn = kv0 + (cur ^ 1) * AKV_BUF;
            const size_t base = kvbase0 + (size_t)(kt + 1) * 64 * KV_DIM;
            const __nv_bfloat16* pKh = kh + base;
            const __nv_bfloat16* pKl = kl + base;
            const __nv_bfloat16* pVh = vhp + base;
            const __nv_bfloat16* pVl = vlp + base;
            for (int c = tid; c < 1024; c += 256) {
                int r = c >> 4, cc = c & 15;
                uint32_t so = r * AQ_ROWB + cc * 16;
                size_t go = (size_t)r * KV_DIM + cc * 8;
                CP_ASYNC16(kvn + 0 * AKV_TILE + so, pKh + go);
                CP_ASYNC16(kvn + 1 * AKV_TILE + so, pKl + go);
                CP_ASYNC16(kvn + 2 * AKV_TILE + so, pVh + go);
                CP_ASYNC16(kvn + 3 * AKV_TILE + so, pVl + go);
            }
            CP_COMMIT();
        }

        const uint32_t sKh = kv0 + cur * AKV_BUF;
        const uint32_t sKl = sKh + AKV_TILE;
        const uint32_t sVh = sKh + 2 * AKV_TILE;
        const uint32_t sVl = sKh + 3 * AKV_TILE;

        // --- S = Q.K^T, bf16 3-pass ---
        float sacc[8][4];
#pragma unroll
        for (int j = 0; j < 8; j++)
#pragma unroll
            for (int e = 0; e < 4; e++) sacc[j][e] = 0.f;

#pragma unroll
        for (int kk = 0; kk < 8; kk++) {
            uint32_t qfh[4], qfl[4], kf[2];
            ldm_x4(qfh, sQh + qa_off + kk * 32);
            ldm_x4(qfl, sQl + qa_off + kk * 32);
#pragma unroll
            for (int j = 0; j < 8; j++) {
                ldm_x2(kf, sKh + j * 8 * AQ_ROWB + kb_row + kk * 32);
                mma16816(sacc[j], qfh, kf);
                mma16816(sacc[j], qfl, kf);
            }
        }
#pragma unroll
        for (int kk = 0; kk < 8; kk++) {
            uint32_t qfh[4], kf[2];
            ldm_x4(qfh, sQh + qa_off + kk * 32);
#pragma unroll
            for (int j = 0; j < 8; j++) {
                ldm_x2(kf, sKl + j * 8 * AQ_ROWB + kb_row + kk * 32);
                mma16816(sacc[j], qfh, kf);
            }
        }

        // --- causal mask (tiles crossing the diagonal for this warp's rows) ---
        if (kt * 64 + 63 > q0 + m0 + g) {
            const int r0l = q0 + m0 + g, r1l = r0l + 8;
            const int cb = kt * 64 + tg * 2;
#pragma unroll
            for (int j = 0; j < 8; j++) {
                const int c0 = cb + j * 8;
                if (c0     > r0l) sacc[j][0] = -1e30f;
                if (c0 + 1 > r0l) sacc[j][1] = -1e30f;
                if (c0     > r1l) sacc[j][2] = -1e30f;
                if (c0 + 1 > r1l) sacc[j][3] = -1e30f;
            }
        }

        // --- online softmax ---
        float mx0 = -1e30f, mx1 = -1e30f;
#pragma unroll
        for (int j = 0; j < 8; j++) {
            mx0 = fmaxf(mx0, fmaxf(sacc[j][0], sacc[j][1]));
            mx1 = fmaxf(mx1, fmaxf(sacc[j][2], sacc[j][3]));
        }
        mx0 = fmaxf(mx0, __shfl_xor_sync(0xffffffffu, mx0, 1));
        mx0 = fmaxf(mx0, __shfl_xor_sync(0xffffffffu, mx0, 2));
        mx1 = fmaxf(mx1, __shfl_xor_sync(0xffffffffu, mx1, 1));
        mx1 = fmaxf(mx1, __shfl_xor_sync(0xffffffffu, mx1, 2));
        const float nm0 = fmaxf(mst0, mx0);
        const float nm1 = fmaxf(mst1, mx1);
        const float a0 = expf(mst0 - nm0);
        const float a1 = expf(mst1 - nm1);
        mst0 = nm0; mst1 = nm1;
        float sum0 = 0.f, sum1 = 0.f;
#pragma unroll
        for (int j = 0; j < 8; j++) {
            sacc[j][0] = expf(sacc[j][0] - nm0);
            sacc[j][1] = expf(sacc[j][1] - nm0);
            sacc[j][2] = expf(sacc[j][2] - nm1);
            sacc[j][3] = expf(sacc[j][3] - nm1);
            sum0 += sacc[j][0] + sacc[j][1];
            sum1 += sacc[j][2] + sacc[j][3];
        }
        sum0 += __shfl_xor_sync(0xffffffffu, sum0, 1);
        sum0 += __shfl_xor_sync(0xffffffffu, sum0, 2);
        sum1 += __shfl_xor_sync(0xffffffffu, sum1, 1);
        sum1 += __shfl_xor_sync(0xffffffffu, sum1, 2);
        lst0 = lst0 * a0 + sum0;
        lst1 = lst1 * a1 + sum1;
#pragma unroll
        for (int nt = 0; nt < 16; nt++) {
            oacc[nt][0] *= a0; oacc[nt][1] *= a0;
            oacc[nt][2] *= a1; oacc[nt][3] *= a1;
        }

        // --- O += P.V with error compensation: Ph.Vh + Ph.Vl + Pl.Vh ---
#pragma unroll
        for (int jk = 0; jk < 4; jk++) {
            uint32_t pfh[4], pfl[4];
#pragma unroll
            for (int q = 0; q < 2; q++) {
                const int j = 2 * jk + q;
#pragma unroll
                for (int pr = 0; pr < 2; pr++) {
                    float p0 = sacc[j][2 * pr], p1 = sacc[j][2 * pr + 1];
                    __nv_bfloat16 b0 = __float2bfloat16(p0);
                    __nv_bfloat16 b1 = __float2bfloat16(p1);
                    pfh[2 * q + pr] = ((uint32_t)__bfloat16_as_ushort(b1) << 16) |
                                      __bfloat16_as_ushort(b0);
                    pfl[2 * q + pr] = packbf(p0 - __bfloat162float(b0),
                                             p1 - __bfloat162float(b1));
                }
            }
            const uint32_t vbase = jk * 16 * AQ_ROWB + v_row;
#pragma unroll
            for (int nt = 0; nt < 16; nt++) {
                uint32_t vfh[2], vfl[2];
                ldm_x2_trans(vfh, sVh + vbase + nt * 16);
                ldm_x2_trans(vfl, sVl + vbase + nt * 16);
                mma16816(oacc[nt], pfh, vfh);
                mma16816(oacc[nt], pfh, vfl);
                mma16816(oacc[nt], pfl, vfh);
            }
        }
        // note: no trailing sync needed — next iteration's top __syncthreads
        // (after CP_WAIT0) orders all warps before the buffer is overwritten
    }

    // --- epilogue: normalize, hi/lo split, store bf16 ---
    const float inv0 = 1.f / lst0;
    const float inv1 = 1.f / lst1;
    const size_t r0g = (size_t)(b * S_LEN + q0 + m0 + g);
    const size_t r1g = r0g + 8;
    const int colb = h * HD + tg * 2;
#pragma unroll
    for (int nt = 0; nt < 16; nt++) {
        float v00 = oacc[nt][0] * inv0, v01 = oacc[nt][1] * inv0;
        float v10 = oacc[nt][2] * inv1, v11 = oacc[nt][3] * inv1;
        __nv_bfloat16 h00 = __float2bfloat16(v00), h01 = __float2bfloat16(v01);
        __nv_bfloat16 h10 = __float2bfloat16(v10), h11 = __float2bfloat16(v11);
        float l00 = v00 - __bfloat162float(h00), l01 = v01 - __bfloat162float(h01);
        float l10 = v10 - __bfloat162float(h10), l11 = v11 - __bfloat162float(h11);
        uint32_t hw0 = ((uint32_t)__bfloat16_as_ushort(h01) << 16) | __bfloat16_as_ushort(h00);
        uint32_t hw1 = ((uint32_t)__bfloat16_as_ushort(h11) << 16) | __bfloat16_as_ushort(h10);
        uint32_t lw0 = packbf(l00, l01);
        uint32_t lw1 = packbf(l10, l11);
        const int cc = colb + nt * 8;
        *(uint32_t*)(oh + r0g * DIM + cc) = hw0;
        *(uint32_t*)(ol + r0g * DIM + cc) = lw0;
        *(uint32_t*)(oh + r1g * DIM + cc) = hw1;
        *(uint32_t*)(ol + r1g * DIM + cc) = lw1;
    }
}

// ---------------- launcher ----------------
extern "C" void kernel_launch(void* const* d_in, const int* in_sizes, int n_in,
                              void* d_out, int out_size)
{
    const float* x  = (const float*)d_in[0];
    const float* wq = (const float*)d_in[1];
    const float* wk = (const float*)d_in[2];
    const float* wv = (const float*)d_in[3];
    const float* wo = (const float*)d_in[4];
    const int* positions = (const int*)d_in[7];
    float* out = (float*)d_out;

    float *pq, *pk, *pv;
    cudaGetSymbolAddress((void**)&pq, g_q);
    cudaGetSymbolAddress((void**)&pk, g_k);
    cudaGetSymbolAddress((void**)&pv, g_v);

    __nv_bfloat16 *xh, *xl, *ah, *al, *pkh, *pkl, *pvh, *pvl;
    __nv_bfloat16 *wqh, *wql, *wkh, *wkl, *wvh, *wvl, *woh, *wol;
    cudaGetSymbolAddress((void**)&xh, g_xh);
    cudaGetSymbolAddress((void**)&xl, g_xl);
    cudaGetSymbolAddress((void**)&ah, g_ah);
    cudaGetSymbolAddress((void**)&al, g_al);
    cudaGetSymbolAddress((void**)&pkh, g_kh);
    cudaGetSymbolAddress((void**)&pkl, g_kl);
    cudaGetSymbolAddress((void**)&pvh, g_vh);
    cudaGetSymbolAddress((void**)&pvl, g_vl);
    cudaGetSymbolAddress((void**)&wqh, g_wqTh);
    cudaGetSymbolAddress((void**)&wql, g_wqTl);
    cudaGetSymbolAddress((void**)&wkh, g_wkTh);
    cudaGetSymbolAddress((void**)&wkl, g_wkTl);
    cudaGetSymbolAddress((void**)&wvh, g_wvTh);
    cudaGetSymbolAddress((void**)&wvl, g_wvTl);
    cudaGetSymbolAddress((void**)&woh, g_woTh);
    cudaGetSymbolAddress((void**)&wol, g_woTl);

    cudaFuncSetAttribute(gemm_mma, cudaFuncAttributeMaxDynamicSharedMemorySize, GT_TOTAL);
    cudaFuncSetAttribute(attn_mma, cudaFuncAttributeMaxDynamicSharedMemorySize, AT_SMEM);

    // interleave transpose->gemm so ncu's fixed skip window lands on a GEMM
    {
        int total = T_TOK * DIM;
        convert_split<<<(total + 255) / 256, 256>>>(x, xh, xl, total);
    }
    transpose_convert<<<dim3(DIM / 32,    DIM / 32), 256>>>(wq, wqh, wql, DIM, DIM);
    gemm_mma<<<dim3(DIM / 128,    T_TOK / 128), 256, GT_TOTAL>>>(xh, xl, wqh, wql, pq, DIM,    DIM);
    transpose_convert<<<dim3(KV_DIM / 32, DIM / 32), 256>>>(wk, wkh, wkl, DIM, KV_DIM);
    gemm_mma<<<dim3(KV_DIM / 128, T_TOK / 128), 256, GT_TOTAL>>>(xh, xl, wkh, wkl, pk, KV_DIM, DIM);
    transpose_convert<<<dim3(KV_DIM / 32, DIM / 32), 256>>>(wv, wvh, wvl, DIM, KV_DIM);
    gemm_mma<<<dim3(KV_DIM / 128, T_TOK / 128), 256, GT_TOTAL>>>(xh, xl, wvh, wvl, pv, KV_DIM, DIM);
    transpose_convert<<<dim3(DIM / 32,    DIM / 32), 256>>>(wo, woh, wol, DIM, DIM);

    // RoPE + split (q scaled by 1/sqrt(HD); x splits reused as q splits), V -> hi/lo bf16
    {
        const float scale = 0.08838834764831845f;
        int total_q = T_TOK * NH * (HD / 2);
        int total_k = T_TOK * NKV * (HD / 2);
        rope_split<<<(total_q + 255) / 256, 256>>>(pq, positions, xh, xl, NH,  scale, total_q);
        rope_split<<<(total_k + 255) / 256, 256>>>(pk, positions, pkh, pkl, NKV, 1.0f, total_k);
        int total_v = T_TOK * KV_DIM;
        convert_split<<<(total_v + 255) / 256, 256>>>(pv, pvh, pvl, total_v);
    }

    // flash attention (writes hi/lo bf16 splits of attn output)
    attn_mma<<<dim3(S_LEN / 128, NH, B_SZ), 256, AT_SMEM>>>(xh, xl, pkh, pkl, pvh, pvl, ah, al);

    // output projection
    gemm_mma<<<dim3(DIM / 128, T_TOK / 128), 256, GT_TOTAL>>>(ah, al, woh, wol, out, DIM, DIM);
}

// round 9
// speedup vs baseline: 1.1149x; 1.1149x over previous
#include <cuda_runtime.h>
#include <cuda_bf16.h>
#include <cuda_fp16.h>
#include <cstdint>
#include <math.h>

// ---------------- problem constants ----------------
#define T_TOK   8192
#define DIM     2048
#define NH      16
#define NKV     8
#define HD      128
#define S_LEN   1024
#define B_SZ    8
#define KV_DIM  1024      // NKV * HD
#define N_REP   2

// ---------------- scratch ----------------
__device__ float g_q[T_TOK * DIM];
__device__ float g_k[T_TOK * KV_DIM];
__device__ float g_v[T_TOK * KV_DIM];

// fp16 hi/lo splits for GEMM activations
__device__ __half g_xh[T_TOK * DIM];
__device__ __half g_xl[T_TOK * DIM];
__device__ __half g_ah[T_TOK * DIM];   // attn out split hi
__device__ __half g_al[T_TOK * DIM];   // attn out split lo
// fp16 transposed weights [N,K] (hi only — 2-pass scheme)
__device__ __half g_wqT[DIM * DIM];
__device__ __half g_wkT[KV_DIM * DIM];
__device__ __half g_wvT[KV_DIM * DIM];
__device__ __half g_woT[DIM * DIM];
// bf16 hi/lo splits for attention operands
__device__ __nv_bfloat16 g_qbh[T_TOK * DIM];
__device__ __nv_bfloat16 g_qbl[T_TOK * DIM];
__device__ __nv_bfloat16 g_kh[T_TOK * KV_DIM];
__device__ __nv_bfloat16 g_kl[T_TOK * KV_DIM];
__device__ __nv_bfloat16 g_vh[T_TOK * KV_DIM];
__device__ __nv_bfloat16 g_vl[T_TOK * KV_DIM];

// ================= low-level helpers (sm_80-class PTX only) =================
__device__ __forceinline__ uint32_t smem_to_u32(const void* smem_ptr) {
    uint32_t addr;
    asm("{ .reg .u64 tmp; cvta.to.shared.u64 tmp, %1; cvt.u32.u64 %0, tmp; }"
        : "=r"(addr) : "l"(smem_ptr));
    return addr;
}

#define CP_ASYNC16(dst_u32, src_ptr) \
    asm volatile("cp.async.cg.shared.global [%0], [%1], 16;" \
                 :: "r"(dst_u32), "l"(src_ptr) : "memory")
#define CP_COMMIT() asm volatile("cp.async.commit_group;" ::: "memory")
#define CP_WAIT0()  asm volatile("cp.async.wait_group 0;" ::: "memory")
#define CP_WAIT1()  asm volatile("cp.async.wait_group 1;" ::: "memory")

__device__ __forceinline__ void ldm_x4(uint32_t* r, uint32_t addr) {
    asm volatile("ldmatrix.sync.aligned.m8n8.x4.shared.b16 {%0,%1,%2,%3}, [%4];"
                 : "=r"(r[0]), "=r"(r[1]), "=r"(r[2]), "=r"(r[3]) : "r"(addr));
}
__device__ __forceinline__ void ldm_x2(uint32_t* r, uint32_t addr) {
    asm volatile("ldmatrix.sync.aligned.m8n8.x2.shared.b16 {%0,%1}, [%2];"
                 : "=r"(r[0]), "=r"(r[1]) : "r"(addr));
}
__device__ __forceinline__ void ldm_x2_trans(uint32_t* r, uint32_t addr) {
    asm volatile("ldmatrix.sync.aligned.m8n8.x2.trans.shared.b16 {%0,%1}, [%2];"
                 : "=r"(r[0]), "=r"(r[1]) : "r"(addr));
}
// bf16 mma (attention)
__device__ __forceinline__ void mma16816(float* c, const uint32_t* a, const uint32_t* b) {
    asm volatile("mma.sync.aligned.m16n8k16.row.col.f32.bf16.bf16.f32 "
                 "{%0,%1,%2,%3}, {%4,%5,%6,%7}, {%8,%9}, {%0,%1,%2,%3};"
                 : "+f"(c[0]), "+f"(c[1]), "+f"(c[2]), "+f"(c[3])
                 : "r"(a[0]), "r"(a[1]), "r"(a[2]), "r"(a[3]), "r"(b[0]), "r"(b[1]));
}
// fp16 mma (GEMMs)
__device__ __forceinline__ void mma16816h(float* c, const uint32_t* a, const uint32_t* b) {
    asm volatile("mma.sync.aligned.m16n8k16.row.col.f32.f16.f16.f32 "
                 "{%0,%1,%2,%3}, {%4,%5,%6,%7}, {%8,%9}, {%0,%1,%2,%3};"
                 : "+f"(c[0]), "+f"(c[1]), "+f"(c[2]), "+f"(c[3])
                 : "r"(a[0]), "r"(a[1]), "r"(a[2]), "r"(a[3]), "r"(b[0]), "r"(b[1]));
}
// pack two fp32 into bf16x2 word: mem-low half = first arg
__device__ __forceinline__ uint32_t packbf(float lo, float hi) {
    uint32_t r;
    asm("cvt.rn.bf16x2.f32 %0, %1, %2;" : "=r"(r) : "f"(hi), "f"(lo));
    return r;
}
// pack two fp32 into f16x2 word: mem-low half = first arg
__device__ __forceinline__ uint32_t packh(float lo, float hi) {
    __half2 h = __floats2half2_rn(lo, hi);
    return *(uint32_t*)&h;
}

// ================= fp16 2-pass mma.sync GEMM =================
// C[M,N] = A[M,K] @ W[K,N];  A as (Ah+Al) fp16 [M,K] K-major, W^T as Bh fp16 [N,K].
// C = Ah*Bh + Al*Bh = A * fp16(W)  (only weight-rounding error).
// CTA tile 128x128, K-tile 32, 3-stage cp.async pipeline.
#define GT_ROWB   80
#define GT_TILE   (128 * GT_ROWB)          // 10240 B
#define GT_STAGE  (3 * GT_TILE)            // Ah, Al, Bh = 30720 B
#define GT_NST    3
#define GT_TOTAL  (GT_NST * GT_STAGE)      // 92160 B -> 2 CTAs/SM

__global__ __launch_bounds__(256, 2)
void gemm_h2(const __half* __restrict__ Ah, const __half* __restrict__ Al,
             const __half* __restrict__ Bh, float* __restrict__ C, int Ncols, int K)
{
    extern __shared__ char smc[];
    const uint32_t sbase = smem_to_u32(smc);

    const int tid  = threadIdx.x;
    const int lane = tid & 31;
    const int wid  = tid >> 5;
    const int bx = blockIdx.x;
    const int by = blockIdx.y;
    const int m0 = (wid & 1) * 64;
    const int n0 = (wid >> 1) * 32;

    // load mapping: per tile 512 16B-chunks, 2 per thread
    const int r0c = tid >> 2,          c0c = tid & 3;
    const int r1c = (tid + 256) >> 2,  c1c = tid & 3;

    const size_t ga0 = (size_t)(by * 128 + r0c) * K + c0c * 8;
    const size_t ga1 = (size_t)(by * 128 + r1c) * K + c1c * 8;
    const size_t gb0 = (size_t)(bx * 128 + r0c) * K + c0c * 8;
    const size_t gb1 = (size_t)(bx * 128 + r1c) * K + c1c * 8;
    const uint32_t so0 = r0c * GT_ROWB + c0c * 16;
    const uint32_t so1 = r1c * GT_ROWB + c1c * 16;

    float acc[4][4][4];
#pragma unroll
    for (int i = 0; i < 4; i++)
#pragma unroll
        for (int j = 0; j < 4; j++)
#pragma unroll
            for (int e = 0; e < 4; e++) acc[i][j][e] = 0.f;

    const int n_kt = K >> 5;   // 64

    const uint32_t a_row = (uint32_t)(m0 + (lane & 15));
    const uint32_t a_coloff = (uint32_t)((lane >> 4) * 16);
    const uint32_t b_row = (uint32_t)(n0 + (lane & 7));
    const uint32_t b_coloff = (uint32_t)(((lane >> 3) & 1) * 16);

#define GLOAD_STAGE(sidx, ko)                                              \
    do {                                                                   \
        const uint32_t st_ = sbase + (sidx) * GT_STAGE;                    \
        CP_ASYNC16(st_ + 0 * GT_TILE + so0, Ah + ga0 + (ko));              \
        CP_ASYNC16(st_ + 0 * GT_TILE + so1, Ah + ga1 + (ko));              \
        CP_ASYNC16(st_ + 1 * GT_TILE + so0, Al + ga0 + (ko));              \
        CP_ASYNC16(st_ + 1 * GT_TILE + so1, Al + ga1 + (ko));              \
        CP_ASYNC16(st_ + 2 * GT_TILE + so0, Bh + gb0 + (ko));              \
        CP_ASYNC16(st_ + 2 * GT_TILE + so1, Bh + gb1 + (ko));              \
        CP_COMMIT();                                                       \
    } while (0)

    // prologue: stages 0 and 1
    GLOAD_STAGE(0, 0);
    GLOAD_STAGE(1, 32);

    int sidx = 0;
    for (int kt = 0; kt < n_kt; kt++) {
        if (kt + 1 < n_kt) { CP_WAIT1(); } else { CP_WAIT0(); }
        __syncthreads();
        if (kt + 2 < n_kt) {
            int sn = sidx + 2; if (sn >= GT_NST) sn -= GT_NST;
            GLOAD_STAGE(sn, (size_t)(kt + 2) * 32);
        }

        const uint32_t st = sbase + sidx * GT_STAGE;
        const uint32_t sAh = st;
        const uint32_t sAl = st + 1 * GT_TILE;
        const uint32_t sBh = st + 2 * GT_TILE;

#pragma unroll
        for (int ks = 0; ks < 2; ks++) {
            const uint32_t kb = ks * 32;
            uint32_t af[4][4], bf[4][2];
#pragma unroll
            for (int mt = 0; mt < 4; mt++)
                ldm_x4(af[mt], sAh + (a_row + mt * 16) * GT_ROWB + kb + a_coloff);
#pragma unroll
            for (int nt = 0; nt < 4; nt++)
                ldm_x2(bf[nt], sBh + (b_row + nt * 8) * GT_ROWB + kb + b_coloff);
#pragma unroll
            for (int mt = 0; mt < 4; mt++)
#pragma unroll
                for (int nt = 0; nt < 4; nt++)
                    mma16816h(acc[mt][nt], af[mt], bf[nt]);
#pragma unroll
            for (int mt = 0; mt < 4; mt++)
                ldm_x4(af[mt], sAl + (a_row + mt * 16) * GT_ROWB + kb + a_coloff);
#pragma unroll
            for (int mt = 0; mt < 4; mt++)
#pragma unroll
                for (int nt = 0; nt < 4; nt++)
                    mma16816h(acc[mt][nt], af[mt], bf[nt]);
        }
        sidx++; if (sidx >= GT_NST) sidx -= GT_NST;
    }

    const int g  = lane >> 2;
    const int tg = (lane & 3) * 2;
#pragma unroll
    for (int mt = 0; mt < 4; mt++) {
        const int r = by * 128 + m0 + mt * 16 + g;
#pragma unroll
        for (int nt = 0; nt < 4; nt++) {
            const int cc = bx * 128 + n0 + nt * 8 + tg;
            *(float2*)(C + (size_t)r * Ncols + cc) =
                make_float2(acc[mt][nt][0], acc[mt][nt][1]);
            *(float2*)(C + (size_t)(r + 8) * Ncols + cc) =
                make_float2(acc[mt][nt][2], acc[mt][nt][3]);
        }
    }
}

// ---------------- fp32 -> fp16 hi/lo split ----------------
__global__ __launch_bounds__(256)
void convert_split_h(const float* __restrict__ X, __half* __restrict__ H,
                     __half* __restrict__ L, int total)
{
    int i = blockIdx.x * blockDim.x + threadIdx.x;
    if (i >= total) return;
    float v = X[i];
    __half h = __float2half_rn(v);
    H[i] = h;
    L[i] = __float2half_rn(v - __half2float(h));
}

// ---------------- fp32 -> bf16 hi/lo split ----------------
__global__ __launch_bounds__(256)
void convert_split(const float* __restrict__ X, __nv_bfloat16* __restrict__ H,
                   __nv_bfloat16* __restrict__ L, int total)
{
    int i = blockIdx.x * blockDim.x + threadIdx.x;
    if (i >= total) return;
    float v = X[i];
    __nv_bfloat16 h = __float2bfloat16(v);
    H[i] = h;
    L[i] = __float2bfloat16(v - __bfloat162float(h));
}

// ---------------- W[K,N] -> W^T fp16 [N,K] ----------------
__global__ __launch_bounds__(256)
void transpose_h(const float* __restrict__ W, __half* __restrict__ Th, int K, int N)
{
    __shared__ float t[32][33];
    int n0 = blockIdx.x * 32, k0 = blockIdx.y * 32;
    int tx = threadIdx.x & 31, ty = threadIdx.x >> 5;
#pragma unroll
    for (int j = 0; j < 4; j++)
        t[ty + j * 8][tx] = W[(size_t)(k0 + ty + j * 8) * N + n0 + tx];
    __syncthreads();
#pragma unroll
    for (int j = 0; j < 4; j++)
        Th[(size_t)(n0 + ty + j * 8) * K + k0 + tx] = __float2half_rn(t[tx][ty + j * 8]);
}

// ---------------- RoPE + bf16 hi/lo split ----------------
__global__ __launch_bounds__(256)
void rope_split(const float* __restrict__ src, const int* __restrict__ positions,
                __nv_bfloat16* __restrict__ H, __nv_bfloat16* __restrict__ L,
                int n_heads, float scale, int total)
{
    int idx = blockIdx.x * blockDim.x + threadIdx.x;
    if (idx >= total) return;
    int pair = idx & 63;
    int h    = (idx >> 6) % n_heads;
    int t    = idx / (64 * n_heads);
    double inv = pow(10000.0, -(double)(2 * pair) / 128.0);
    double ang = (double)positions[t] * inv;
    float c = (float)cos(ang);
    float s = (float)sin(ang);
    size_t o = (size_t)t * (n_heads * HD) + h * HD + 2 * pair;
    float xr = src[o], xi = src[o + 1];
    float vr = (xr * c - xi * s) * scale;
    float vi = (xr * s + xi * c) * scale;
    __nv_bfloat16 hr = __float2bfloat16(vr);
    __nv_bfloat16 hi = __float2bfloat16(vi);
    H[o]     = hr;
    H[o + 1] = hi;
    L[o]     = __float2bfloat16(vr - __bfloat162float(hr));
    L[o + 1] = __float2bfloat16(vi - __bfloat162float(hi));
}

// ================= mma.sync flash attention (causal, GQA rep=2) =================
// BQ=128, BK=64. grid (S/128, NH, B), 256 threads (8 warps; warp w owns q rows w*16..+15).
// smem: Qh,Ql [128][128]bf16 + double-buffered Kh,Kl,Vh,Vl [64][128]bf16; row stride 272 B.
#define AQ_ROWB 272
#define AQ_TILE (128 * AQ_ROWB)        // 34816
#define AKV_TILE (64 * AQ_ROWB)        // 17408
#define AKV_BUF (4 * AKV_TILE)         // 69632
#define AT_SMEM (2 * AQ_TILE + 2 * AKV_BUF)   // 208896 B -> 1 CTA/SM

__global__ __launch_bounds__(256, 1)
void attn_mma(const __nv_bfloat16* __restrict__ qh, const __nv_bfloat16* __restrict__ ql,
              const __nv_bfloat16* __restrict__ kh, const __nv_bfloat16* __restrict__ kl,
              const __nv_bfloat16* __restrict__ vhp, const __nv_bfloat16* __restrict__ vlp,
              __half* __restrict__ oh, __half* __restrict__ ol)
{
    extern __shared__ char smb[];
    const uint32_t sb  = smem_to_u32(smb);
    const uint32_t sQh = sb;
    const uint32_t sQl = sb + AQ_TILE;
    const uint32_t kv0 = sb + 2 * AQ_TILE;

    const int tid  = threadIdx.x;
    const int lane = tid & 31;
    const int wid  = tid >> 5;
    const int qt = blockIdx.x, h = blockIdx.y, b = blockIdx.z;
    const int kvh = h >> 1;
    const int q0 = qt * 128;
    const int m0 = wid * 16;
    const int g  = lane >> 2;
    const int tg = lane & 3;

    // --- Q tiles (hi+lo), 128 rows, loaded once ---
    {
        const __nv_bfloat16* srcH = qh + (size_t)(b * S_LEN + q0) * DIM + h * HD;
        const __nv_bfloat16* srcL = ql + (size_t)(b * S_LEN + q0) * DIM + h * HD;
        for (int c = tid; c < 2048; c += 256) {
            int r = c >> 4, cc = c & 15;
            CP_ASYNC16(sQh + r * AQ_ROWB + cc * 16, srcH + (size_t)r * DIM + cc * 8);
            CP_ASYNC16(sQl + r * AQ_ROWB + cc * 16, srcL + (size_t)r * DIM + cc * 8);
        }
        CP_COMMIT();
    }

    const size_t kvbase0 = (size_t)(b * S_LEN) * KV_DIM + kvh * HD;

    // prologue: KV tile 0 -> buffer 0
    {
        const __nv_bfloat16* pKh = kh + kvbase0;
        const __nv_bfloat16* pKl = kl + kvbase0;
        const __nv_bfloat16* pVh = vhp + kvbase0;
        const __nv_bfloat16* pVl = vlp + kvbase0;
        for (int c = tid; c < 1024; c += 256) {
            int r = c >> 4, cc = c & 15;
            uint32_t so = r * AQ_ROWB + cc * 16;
            size_t go = (size_t)r * KV_DIM + cc * 8;
            CP_ASYNC16(kv0 + 0 * AKV_TILE + so, pKh + go);
            CP_ASYNC16(kv0 + 1 * AKV_TILE + so, pKl + go);
            CP_ASYNC16(kv0 + 2 * AKV_TILE + so, pVh + go);
            CP_ASYNC16(kv0 + 3 * AKV_TILE + so, pVl + go);
        }
        CP_COMMIT();
    }

    float oacc[16][4];
#pragma unroll
    for (int nt = 0; nt < 16; nt++)
#pragma unroll
        for (int e = 0; e < 4; e++) oacc[nt][e] = 0.f;
    float mst0 = -1e30f, mst1 = -1e30f, lst0 = 0.f, lst1 = 0.f;

    const uint32_t qa_off = (uint32_t)((m0 + (lane & 15)) * AQ_ROWB + (lane >> 4) * 16);
    const uint32_t kb_row = (uint32_t)((lane & 7) * AQ_ROWB + ((lane >> 3) & 1) * 16);
    const uint32_t v_row  = (uint32_t)((lane & 15) * AQ_ROWB);

    const int ktmax = 2 * qt + 1;
    for (int kt = 0; kt <= ktmax; kt++) {
        const int cur = kt & 1;
        CP_WAIT0();
        __syncthreads();

        // prefetch next KV tile into the other buffer
        if (kt < ktmax) {
            const uint32_t kvn = kv0 + (cur ^ 1) * AKV_BUF;
            const size_t base = kvbase0 + (size_t)(kt + 1) * 64 * KV_DIM;
            const __nv_bfloat16* pKh = kh + base;
            const __nv_bfloat16* pKl = kl + base;
            const __nv_bfloat16* pVh = vhp + base;
            const __nv_bfloat16* pVl = vlp + base;
            for (int c = tid; c < 1024; c += 256) {
                int r = c >> 4, cc = c & 15;
                uint32_t so = r * AQ_ROWB + cc * 16;
                size_t go = (size_t)r * KV_DIM + cc * 8;
                CP_ASYNC16(kvn + 0 * AKV_TILE + so, pKh + go);
                CP_ASYNC16(kvn + 1 * AKV_TILE + so, pKl + go);
                CP_ASYNC16(kvn + 2 * AKV_TILE + so, pVh + go);
                CP_ASYNC16(kvn + 3 * AKV_TILE + so, pVl + go);
            }
            CP_COMMIT();
        }

        const uint32_t sKh = kv0 + cur * AKV_BUF;
        const uint32_t sKl = sKh + AKV_TILE;
        const uint32_t sVh = sKh + 2 * AKV_TILE;
        const uint32_t sVl = sKh + 3 * AKV_TILE;

        // --- S = Q.K^T, bf16 3-pass ---
        float sacc[8][4];
#pragma unroll
        for (int j = 0; j < 8; j++)
#pragma unroll
            for (int e = 0; e < 4; e++) sacc[j][e] = 0.f;

#pragma unroll
        for (int kk = 0; kk < 8; kk++) {
            uint32_t qfh[4], qfl[4], kf[2];
            ldm_x4(qfh, sQh + qa_off + kk * 32);
            ldm_x4(qfl, sQl + qa_off + kk * 32);
#pragma unroll
            for (int j = 0; j < 8; j++) {
                ldm_x2(kf, sKh + j * 8 * AQ_ROWB + kb_row + kk * 32);
                mma16816(sacc[j], qfh, kf);
                mma16816(sacc[j], qfl, kf);
            }
        }
#pragma unroll
        for (int kk = 0; kk < 8; kk++) {
            uint32_t qfh[4], kf[2];
            ldm_x4(qfh, sQh + qa_off + kk * 32);
#pragma unroll
            for (int j = 0; j < 8; j++) {
                ldm_x2(kf, sKl + j * 8 * AQ_ROWB + kb_row + kk * 32);
                mma16816(sacc[j], qfh, kf);
            }
        }

        // --- causal mask ---
        if (kt * 64 + 63 > q0 + m0 + g) {
            const int r0l = q0 + m0 + g, r1l = r0l + 8;
            const int cb = kt * 64 + tg * 2;
#pragma unroll
            for (int j = 0; j < 8; j++) {
                const int c0 = cb + j * 8;
                if (c0     > r0l) sacc[j][0] = -1e30f;
                if (c0 + 1 > r0l) sacc[j][1] = -1e30f;
                if (c0     > r1l) sacc[j][2] = -1e30f;
                if (c0 + 1 > r1l) sacc[j][3] = -1e30f;
            }
        }

        // --- online softmax ---
        float mx0 = -1e30f, mx1 = -1e30f;
#pragma unroll
        for (int j = 0; j < 8; j++) {
            mx0 = fmaxf(mx0, fmaxf(sacc[j][0], sacc[j][1]));
            mx1 = fmaxf(mx1, fmaxf(sacc[j][2], sacc[j][3]));
        }
        mx0 = fmaxf(mx0, __shfl_xor_sync(0xffffffffu, mx0, 1));
        mx0 = fmaxf(mx0, __shfl_xor_sync(0xffffffffu, mx0, 2));
        mx1 = fmaxf(mx1, __shfl_xor_sync(0xffffffffu, mx1, 1));
        mx1 = fmaxf(mx1, __shfl_xor_sync(0xffffffffu, mx1, 2));
        const float nm0 = fmaxf(mst0, mx0);
        const float nm1 = fmaxf(mst1, mx1);
        const float a0 = expf(mst0 - nm0);
        const float a1 = expf(mst1 - nm1);
        mst0 = nm0; mst1 = nm1;
        float sum0 = 0.f, sum1 = 0.f;
#pragma unroll
        for (int j = 0; j < 8; j++) {
            sacc[j][0] = expf(sacc[j][0] - nm0);
            sacc[j][1] = expf(sacc[j][1] - nm0);
            sacc[j][2] = expf(sacc[j][2] - nm1);
            sacc[j][3] = expf(sacc[j][3] - nm1);
            sum0 += sacc[j][0] + sacc[j][1];
            sum1 += sacc[j][2] + sacc[j][3];
        }
        sum0 += __shfl_xor_sync(0xffffffffu, sum0, 1);
        sum0 += __shfl_xor_sync(0xffffffffu, sum0, 2);
        sum1 += __shfl_xor_sync(0xffffffffu, sum1, 1);
        sum1 += __shfl_xor_sync(0xffffffffu, sum1, 2);
        lst0 = lst0 * a0 + sum0;
        lst1 = lst1 * a1 + sum1;
#pragma unroll
        for (int nt = 0; nt < 16; nt++) {
            oacc[nt][0] *= a0; oacc[nt][1] *= a0;
            oacc[nt][2] *= a1; oacc[nt][3] *= a1;
        }

        // --- O += P.V with error compensation: Ph.Vh + Ph.Vl + Pl.Vh ---
#pragma unroll
        for (int jk = 0; jk < 4; jk++) {
            uint32_t pfh[4], pfl[4];
#pragma unroll
            for (int q = 0; q < 2; q++) {
                const int j = 2 * jk + q;
#pragma unroll
                for (int pr = 0; pr < 2; pr++) {
                    float p0 = sacc[j][2 * pr], p1 = sacc[j][2 * pr + 1];
                    __nv_bfloat16 b0 = __float2bfloat16(p0);
                    __nv_bfloat16 b1 = __float2bfloat16(p1);
                    pfh[2 * q + pr] = ((uint32_t)__bfloat16_as_ushort(b1) << 16) |
                                      __bfloat16_as_ushort(b0);
                    pfl[2 * q + pr] = packbf(p0 - __bfloat162float(b0),
                                             p1 - __bfloat162float(b1));
                }
            }
            const uint32_t vbase = jk * 16 * AQ_ROWB + v_row;
#pragma unroll
            for (int nt = 0; nt < 16; nt++) {
                uint32_t vfh[2], vfl[2];
                ldm_x2_trans(vfh, sVh + vbase + nt * 16);
                ldm_x2_trans(vfl, sVl + vbase + nt * 16);
                mma16816(oacc[nt], pfh, vfh);
                mma16816(oacc[nt], pfh, vfl);
                mma16816(oacc[nt], pfl, vfh);
            }
        }
    }

    // --- epilogue: normalize, fp16 hi/lo split, store ---
    const float inv0 = 1.f / lst0;
    const float inv1 = 1.f / lst1;
    const size_t r0g = (size_t)(b * S_LEN + q0 + m0 + g);
    const size_t r1g = r0g + 8;
    const int colb = h * HD + tg * 2;
#pragma unroll
    for (int nt = 0; nt < 16; nt++) {
        float v00 = oacc[nt][0] * inv0, v01 = oacc[nt][1] * inv0;
        float v10 = oacc[nt][2] * inv1, v11 = oacc[nt][3] * inv1;
        __half h00 = __float2half_rn(v00), h01 = __float2half_rn(v01);
        __half h10 = __float2half_rn(v10), h11 = __float2half_rn(v11);
        uint32_t hw0, hw1;
        { __half2 t2 = __halves2half2(h00, h01); hw0 = *(uint32_t*)&t2; }
        { __half2 t2 = __halves2half2(h10, h11); hw1 = *(uint32_t*)&t2; }
        uint32_t lw0 = packh(v00 - __half2float(h00), v01 - __half2float(h01));
        uint32_t lw1 = packh(v10 - __half2float(h10), v11 - __half2float(h11));
        const int cc = colb + nt * 8;
        *(uint32_t*)(oh + r0g * DIM + cc) = hw0;
        *(uint32_t*)(ol + r0g * DIM + cc) = lw0;
        *(uint32_t*)(oh + r1g * DIM + cc) = hw1;
        *(uint32_t*)(ol + r1g * DIM + cc) = lw1;
    }
}

// ---------------- launcher ----------------
extern "C" void kernel_launch(void* const* d_in, const int* in_sizes, int n_in,
                              void* d_out, int out_size)
{
    const float* x  = (const float*)d_in[0];
    const float* wq = (const float*)d_in[1];
    const float* wk = (const float*)d_in[2];
    const float* wv = (const float*)d_in[3];
    const float* wo = (const float*)d_in[4];
    const int* positions = (const int*)d_in[7];
    float* out = (float*)d_out;

    float *pq, *pk, *pv;
    cudaGetSymbolAddress((void**)&pq, g_q);
    cudaGetSymbolAddress((void**)&pk, g_k);
    cudaGetSymbolAddress((void**)&pv, g_v);

    __half *xh, *xl, *ah, *al, *wqT, *wkT, *wvT, *woT;
    __nv_bfloat16 *qbh, *qbl, *pkh, *pkl, *pvh, *pvl;
    cudaGetSymbolAddress((void**)&xh, g_xh);
    cudaGetSymbolAddress((void**)&xl, g_xl);
    cudaGetSymbolAddress((void**)&ah, g_ah);
    cudaGetSymbolAddress((void**)&al, g_al);
    cudaGetSymbolAddress((void**)&wqT, g_wqT);
    cudaGetSymbolAddress((void**)&wkT, g_wkT);
    cudaGetSymbolAddress((void**)&wvT, g_wvT);
    cudaGetSymbolAddress((void**)&woT, g_woT);
    cudaGetSymbolAddress((void**)&qbh, g_qbh);
    cudaGetSymbolAddress((void**)&qbl, g_qbl);
    cudaGetSymbolAddress((void**)&pkh, g_kh);
    cudaGetSymbolAddress((void**)&pkl, g_kl);
    cudaGetSymbolAddress((void**)&pvh, g_vh);
    cudaGetSymbolAddress((void**)&pvl, g_vl);

    cudaFuncSetAttribute(gemm_h2,  cudaFuncAttributeMaxDynamicSharedMemorySize, GT_TOTAL);
    cudaFuncSetAttribute(attn_mma, cudaFuncAttributeMaxDynamicSharedMemorySize, AT_SMEM);

    // launches 1-5: converts/transposes.  launch #6 = Q GEMM (ncu -s 5 -c 1 captures it)
    {
        int total = T_TOK * DIM;
        convert_split_h<<<(total + 255) / 256, 256>>>(x, xh, xl, total);          // 1
    }
    transpose_h<<<dim3(DIM / 32,    DIM / 32), 256>>>(wq, wqT, DIM, DIM);          // 2
    transpose_h<<<dim3(KV_DIM / 32, DIM / 32), 256>>>(wk, wkT, DIM, KV_DIM);       // 3
    transpose_h<<<dim3(KV_DIM / 32, DIM / 32), 256>>>(wv, wvT, DIM, KV_DIM);       // 4
    transpose_h<<<dim3(DIM / 32,    DIM / 32), 256>>>(wo, woT, DIM, DIM);          // 5

    gemm_h2<<<dim3(DIM / 128,    T_TOK / 128), 256, GT_TOTAL>>>(xh, xl, wqT, pq, DIM,    DIM);  // 6
    gemm_h2<<<dim3(KV_DIM / 128, T_TOK / 128), 256, GT_TOTAL>>>(xh, xl, wkT, pk, KV_DIM, DIM);  // 7
    gemm_h2<<<dim3(KV_DIM / 128, T_TOK / 128), 256, GT_TOTAL>>>(xh, xl, wvT, pv, KV_DIM, DIM);  // 8

    // RoPE + bf16 split for attention (q scaled by 1/sqrt(HD)); V -> bf16 hi/lo
    {
        const float scale = 0.08838834764831845f;
        int total_q = T_TOK * NH * (HD / 2);
        int total_k = T_TOK * NKV * (HD / 2);
        rope_split<<<(total_q + 255) / 256, 256>>>(pq, positions, qbh, qbl, NH,  scale, total_q);
        rope_split<<<(total_k + 255) / 256, 256>>>(pk, positions, pkh, pkl, NKV, 1.0f, total_k);
        int total_v = T_TOK * KV_DIM;
        convert_split<<<(total_v + 255) / 256, 256>>>(pv, pvh, pvl, total_v);
    }

    // flash attention (writes fp16 hi/lo splits of attn output)
    attn_mma<<<dim3(S_LEN / 128, NH, B_SZ), 256, AT_SMEM>>>(qbh, qbl, pkh, pkl, pvh, pvl, ah, al);

    // output projection
    gemm_h2<<<dim3(DIM / 128, T_TOK / 128), 256, GT_TOTAL>>>(ah, al, woT, out, DIM, DIM);
}